// round 10
// baseline (speedup 1.0000x reference)
#include <cuda_runtime.h>
#include <cuda_bf16.h>
#include <math.h>

// Problem constants
#define BB   64
#define HH   512
#define EE   256
#define VV   20000
#define TSRC 200
#define TTRG 128
#define EIDSLAB  ((long long)BB * VV)             // floats per output timestep
#define RATEBASE ((long long)TTRG * BB * VV)      // offset of rate block in d_out

// ---------------- device scratch (static; no runtime allocation) ----------------
__device__ float g_hA[BB * HH];
__device__ float g_hB[BB * HH];
__device__ int   g_eid[BB];
__device__ float g_rate[BB];

// ---------------- packed fp32x2 helpers (sm_103a FMA2 path) ----------------
__device__ __forceinline__ unsigned long long pk2(float a, float b) {
    unsigned long long r;
    asm("mov.b64 %0, {%1,%2};" : "=l"(r) : "f"(a), "f"(b));
    return r;
}
__device__ __forceinline__ void fma2(unsigned long long& acc,
                                     unsigned long long a, unsigned long long w) {
    asm("fma.rn.f32x2 %0, %1, %2, %0;" : "+l"(acc) : "l"(a), "l"(w));
}
__device__ __forceinline__ float upk2(unsigned long long a) {
    float lo = __uint_as_float((unsigned)a);
    float hi = __uint_as_float((unsigned)(a >> 32));
    return lo + hi;
}
__device__ __forceinline__ float sigm(float x) { return 1.0f / (1.0f + expf(-x)); }

// =================================================================================
// prep: zero step-0 output slabs, init h0, eid0, rate0
// =================================================================================
__global__ void prep_kernel(float* __restrict__ out,
                            const int* __restrict__ trg_eid,
                            const float* __restrict__ trg_rate) {
    long long i = (long long)blockIdx.x * 256 + threadIdx.x;
    if (i < EIDSLAB) out[i] = 0.0f;
    if (i < BB) {
        out[RATEBASE + i] = 0.0f;
        g_eid[i]  = trg_eid[i];
        g_rate[i] = trg_rate[i];
    }
    if (i < BB * HH) g_hA[i] = 0.0f;
}

// =================================================================================
// Encoder GRU step. grid 128 x 256 threads. thread = (b, jj); block covers 4 h-cols.
// =================================================================================
__global__ __launch_bounds__(256) void enc_gru_kernel(
    const float* __restrict__ src,     // [200][64][3]
    const int*   __restrict__ src_len, // [64]
    const float* __restrict__ Wih,     // [1536][3]
    const float* __restrict__ Whh,     // [1536][512]
    const float* __restrict__ bih,
    const float* __restrict__ bhh,
    int t, int dir)
{
    const float* hin  = dir ? g_hB : g_hA;
    float*       hout = dir ? g_hA : g_hB;

    __shared__ __align__(16) float Hs[64 * 34];   // [b][k], stride 34 (8B-aligned pairs)
    __shared__ __align__(16) float Ws[12 * 34];   // 3 gates x 4 cols

    int tid = threadIdx.x;
    int b  = tid & 63;
    int jj = tid >> 6;
    int j0 = blockIdx.x * 4;
    int j  = j0 + jj;

    unsigned long long a0 = 0ull, a1 = 0ull, a2 = 0ull;

    for (int k0 = 0; k0 < HH; k0 += 32) {
        __syncthreads();
        #pragma unroll
        for (int p = 0; p < 8; p++) {
            int idx = tid + p * 256;
            int r = idx >> 5, k = idx & 31;
            Hs[r * 34 + k] = hin[r * HH + k0 + k];
        }
        for (int idx = tid; idx < 384; idx += 256) {
            int wr = idx >> 5, k = idx & 31;
            Ws[wr * 34 + k] = Whh[((wr >> 2) * HH + j0 + (wr & 3)) * HH + k0 + k];
        }
        __syncthreads();
        #pragma unroll
        for (int kp = 0; kp < 16; kp++) {
            unsigned long long a = *(const unsigned long long*)&Hs[b * 34 + 2 * kp];
            fma2(a0, a, *(const unsigned long long*)&Ws[jj * 34 + 2 * kp]);
            fma2(a1, a, *(const unsigned long long*)&Ws[(4 + jj) * 34 + 2 * kp]);
            fma2(a2, a, *(const unsigned long long*)&Ws[(8 + jj) * 34 + 2 * kp]);
        }
    }

    const float* xt = src + ((long long)t * BB + b) * 3;
    float x0 = xt[0], x1 = xt[1], x2 = xt[2];
    int rr = j, rz = HH + j, rn = 2 * HH + j;
    float gir = bih[rr] + x0 * Wih[rr * 3] + x1 * Wih[rr * 3 + 1] + x2 * Wih[rr * 3 + 2];
    float giz = bih[rz] + x0 * Wih[rz * 3] + x1 * Wih[rz * 3 + 1] + x2 * Wih[rz * 3 + 2];
    float gin = bih[rn] + x0 * Wih[rn * 3] + x1 * Wih[rn * 3 + 1] + x2 * Wih[rn * 3 + 2];

    float ghr = upk2(a0) + bhh[rr];
    float ghz = upk2(a1) + bhh[rz];
    float ghn = upk2(a2) + bhh[rn];

    float r = sigm(gir + ghr);
    float z = sigm(giz + ghz);
    float n = tanhf(gin + r * ghn);
    float hprev = hin[b * HH + j];
    float hnew  = (1.0f - z) * n + z * hprev;
    hout[b * HH + j] = (t < src_len[b]) ? hnew : hprev;
}

// =================================================================================
// Decoder GRU step. K = 512 (Whh over h) + 257 (Wih over [emb[eid], rate]).
// =================================================================================
__global__ __launch_bounds__(256) void dec_gru_kernel(
    const float* __restrict__ emb,     // [20000][256]
    const float* __restrict__ Wih,     // [1536][257]
    const float* __restrict__ Whh,     // [1536][512]
    const float* __restrict__ bih,
    const float* __restrict__ bhh,
    int dir)
{
    const float* hin  = dir ? g_hB : g_hA;
    float*       hout = dir ? g_hA : g_hB;

    __shared__ __align__(16) float Hs[64 * 34];
    __shared__ __align__(16) float Ws[12 * 34];

    int tid = threadIdx.x;
    int b  = tid & 63;
    int jj = tid >> 6;
    int j0 = blockIdx.x * 4;
    int j  = j0 + jj;

    unsigned long long aH0 = 0, aH1 = 0, aH2 = 0;
    unsigned long long aI0 = 0, aI1 = 0, aI2 = 0;

    // ---- h @ Whh^T part (K = 512) ----
    for (int k0 = 0; k0 < HH; k0 += 32) {
        __syncthreads();
        #pragma unroll
        for (int p = 0; p < 8; p++) {
            int idx = tid + p * 256;
            int r = idx >> 5, k = idx & 31;
            Hs[r * 34 + k] = hin[r * HH + k0 + k];
        }
        for (int idx = tid; idx < 384; idx += 256) {
            int wr = idx >> 5, k = idx & 31;
            Ws[wr * 34 + k] = Whh[((wr >> 2) * HH + j0 + (wr & 3)) * HH + k0 + k];
        }
        __syncthreads();
        #pragma unroll
        for (int kp = 0; kp < 16; kp++) {
            unsigned long long a = *(const unsigned long long*)&Hs[b * 34 + 2 * kp];
            fma2(aH0, a, *(const unsigned long long*)&Ws[jj * 34 + 2 * kp]);
            fma2(aH1, a, *(const unsigned long long*)&Ws[(4 + jj) * 34 + 2 * kp]);
            fma2(aH2, a, *(const unsigned long long*)&Ws[(8 + jj) * 34 + 2 * kp]);
        }
    }

    // ---- emb[eid] @ Wih^T part (K = 256; Wih row stride 257) ----
    for (int k0 = 0; k0 < EE; k0 += 32) {
        __syncthreads();
        #pragma unroll
        for (int p = 0; p < 8; p++) {
            int idx = tid + p * 256;
            int r = idx >> 5, k = idx & 31;
            Hs[r * 34 + k] = emb[(long long)g_eid[r] * EE + k0 + k];
        }
        for (int idx = tid; idx < 384; idx += 256) {
            int wr = idx >> 5, k = idx & 31;
            Ws[wr * 34 + k] = Wih[((wr >> 2) * HH + j0 + (wr & 3)) * 257 + k0 + k];
        }
        __syncthreads();
        #pragma unroll
        for (int kp = 0; kp < 16; kp++) {
            unsigned long long a = *(const unsigned long long*)&Hs[b * 34 + 2 * kp];
            fma2(aI0, a, *(const unsigned long long*)&Ws[jj * 34 + 2 * kp]);
            fma2(aI1, a, *(const unsigned long long*)&Ws[(4 + jj) * 34 + 2 * kp]);
            fma2(aI2, a, *(const unsigned long long*)&Ws[(8 + jj) * 34 + 2 * kp]);
        }
    }

    int rr = j, rz = HH + j, rn = 2 * HH + j;
    float rate = g_rate[b];
    float gir = upk2(aI0) + bih[rr] + rate * Wih[rr * 257 + 256];
    float giz = upk2(aI1) + bih[rz] + rate * Wih[rz * 257 + 256];
    float gin = upk2(aI2) + bih[rn] + rate * Wih[rn * 257 + 256];
    float ghr = upk2(aH0) + bhh[rr];
    float ghz = upk2(aH1) + bhh[rz];
    float ghn = upk2(aH2) + bhh[rn];

    float r = sigm(gir + ghr);
    float z = sigm(giz + ghz);
    float n = tanhf(gin + r * ghn);
    float hprev = hin[b * HH + j];
    hout[b * HH + j] = (1.0f - z) * n + z * hprev;
}

// =================================================================================
// pe GEMM: logits[b][v] = dot(h[b], pe_W[v]) + pe_b[v] -> written into out slab t+1.
// grid 157 x 256 threads; tile 64b x 128v; thread = 8b x 4v packed accumulators.
// =================================================================================
__global__ __launch_bounds__(256) void pe_gemm_kernel(
    const float* __restrict__ peW,   // [20000][512]
    const float* __restrict__ peB,   // [20000]
    float* __restrict__ out, int t, int hsel)
{
    const float* h = hsel ? g_hB : g_hA;

    __shared__ __align__(16) float Hs[64 * 34];
    __shared__ __align__(16) float Ws[128 * 34];

    int tid = threadIdx.x;
    int ty = tid >> 5;           // 0..7 -> b group
    int tx = tid & 31;           // v lane
    int b0 = ty * 8;
    int v0 = blockIdx.x * 128;

    unsigned long long acc[8][4];
    #pragma unroll
    for (int i = 0; i < 8; i++)
        #pragma unroll
        for (int jv = 0; jv < 4; jv++) acc[i][jv] = 0ull;

    for (int k0 = 0; k0 < HH; k0 += 32) {
        __syncthreads();
        #pragma unroll
        for (int p = 0; p < 8; p++) {
            int idx = tid + p * 256;
            int r = idx >> 5, k = idx & 31;
            Hs[r * 34 + k] = h[r * HH + k0 + k];
        }
        #pragma unroll
        for (int p = 0; p < 16; p++) {
            int idx = tid + p * 256;
            int r = idx >> 5, k = idx & 31;
            int v = v0 + r;
            Ws[r * 34 + k] = (v < VV) ? peW[v * HH + k0 + k] : 0.0f;
        }
        __syncthreads();
        #pragma unroll
        for (int kp = 0; kp < 16; kp++) {
            unsigned long long a[8], w[4];
            #pragma unroll
            for (int i = 0; i < 8; i++)
                a[i] = *(const unsigned long long*)&Hs[(b0 + i) * 34 + 2 * kp];
            #pragma unroll
            for (int jv = 0; jv < 4; jv++)
                w[jv] = *(const unsigned long long*)&Ws[(tx + 32 * jv) * 34 + 2 * kp];
            #pragma unroll
            for (int i = 0; i < 8; i++)
                #pragma unroll
                for (int jv = 0; jv < 4; jv++)
                    fma2(acc[i][jv], a[i], w[jv]);
        }
    }

    long long slab = (long long)(t + 1) * EIDSLAB;
    #pragma unroll
    for (int jv = 0; jv < 4; jv++) {
        int v = v0 + tx + 32 * jv;
        if (v < VV) {
            float bias = peB[v];
            #pragma unroll
            for (int i = 0; i < 8; i++)
                out[slab + (long long)(b0 + i) * VV + v] = upk2(acc[i][jv]) + bias;
        }
    }
}

// =================================================================================
// Fused log_softmax + argmax per row. grid 64 x 1024 threads, 20 logits/thread
// held in registers; single global read + single write. Writes g_eid.
// =================================================================================
__global__ __launch_bounds__(1024) void softmax_argmax_kernel(float* __restrict__ out, int t)
{
    int b   = blockIdx.x;
    int tid = threadIdx.x;
    float* row = out + (long long)(t + 1) * EIDSLAB + (long long)b * VV;

    float vals[20];
    float m = -INFINITY;
    int   mi = 0;
    #pragma unroll
    for (int i = 0; i < 20; i++) {
        int idx = tid + (i << 10);
        float v = (idx < VV) ? row[idx] : -INFINITY;
        vals[i] = v;
        if (v > m) { m = v; mi = idx; }
    }

    __shared__ float sm[32];
    __shared__ int   si[32];
    __shared__ float g0, g1;
    __shared__ int   gidx;

    int wid = tid >> 5, lane = tid & 31;
    #pragma unroll
    for (int off = 16; off; off >>= 1) {
        float om = __shfl_down_sync(0xffffffffu, m, off);
        int   oi = __shfl_down_sync(0xffffffffu, mi, off);
        if (om > m || (om == m && oi < mi)) { m = om; mi = oi; }
    }
    if (lane == 0) { sm[wid] = m; si[wid] = mi; }
    __syncthreads();
    if (wid == 0) {
        m  = sm[lane];
        mi = si[lane];
        #pragma unroll
        for (int off = 16; off; off >>= 1) {
            float om = __shfl_down_sync(0xffffffffu, m, off);
            int   oi = __shfl_down_sync(0xffffffffu, mi, off);
            if (om > m || (om == m && oi < mi)) { m = om; mi = oi; }
        }
        if (lane == 0) { g0 = m; gidx = mi; }
    }
    __syncthreads();
    float gmax = g0;

    float s = 0.0f;
    #pragma unroll
    for (int i = 0; i < 20; i++) {
        int idx = tid + (i << 10);
        if (idx < VV) s += expf(vals[i] - gmax);
    }
    #pragma unroll
    for (int off = 16; off; off >>= 1)
        s += __shfl_down_sync(0xffffffffu, s, off);
    if (lane == 0) sm[wid] = s;
    __syncthreads();
    if (wid == 0) {
        s = sm[lane];
        #pragma unroll
        for (int off = 16; off; off >>= 1)
            s += __shfl_down_sync(0xffffffffu, s, off);
        if (lane == 0) g1 = gmax + logf(s);
    }
    __syncthreads();
    float logZ = g1;

    #pragma unroll
    for (int i = 0; i < 20; i++) {
        int idx = tid + (i << 10);
        if (idx < VV) row[idx] = vals[i] - logZ;
    }
    if (tid == 0) g_eid[b] = gidx;
}

// =================================================================================
// r1 = relu([emb[idx], h] @ r1_W^T + r1_b); rate = sigmoid(r1 . r2_W + r2_b).
// grid 64 (one block per b) x 512 threads (one per r1 column).
// =================================================================================
__global__ __launch_bounds__(512) void r1rate_kernel(
    const float* __restrict__ emb,
    const float* __restrict__ r1W,   // [512][768]
    const float* __restrict__ r1b,
    const float* __restrict__ r2W,   // [1][512]
    const float* __restrict__ r2b,
    float* __restrict__ out, int t, int hsel)
{
    const float* h = hsel ? g_hB : g_hA;
    int b   = blockIdx.x;
    int tid = threadIdx.x;

    __shared__ __align__(16) float Xs[768];
    __shared__ float sred[16];

    if (tid < 256) Xs[tid] = emb[(long long)g_eid[b] * EE + tid];
    Xs[256 + tid] = h[b * HH + tid];
    __syncthreads();

    const float4* wp = (const float4*)(r1W + tid * 768);
    unsigned long long a0 = 0ull, a1 = 0ull;
    #pragma unroll 4
    for (int q = 0; q < 192; q++) {
        float4 w4 = wp[q];
        float4 x4 = *(const float4*)&Xs[4 * q];
        fma2(a0, pk2(x4.x, x4.y), pk2(w4.x, w4.y));
        fma2(a1, pk2(x4.z, x4.w), pk2(w4.z, w4.w));
    }
    float r1v = upk2(a0) + upk2(a1) + r1b[tid];
    float s = fmaxf(r1v, 0.0f) * r2W[tid];

    int lane = tid & 31, wid = tid >> 5;
    #pragma unroll
    for (int off = 16; off; off >>= 1)
        s += __shfl_down_sync(0xffffffffu, s, off);
    if (lane == 0) sred[wid] = s;
    __syncthreads();
    if (tid < 32) {
        float v = (tid < 16) ? sred[tid] : 0.0f;
        #pragma unroll
        for (int off = 8; off; off >>= 1)
            v += __shfl_down_sync(0xffffffffu, v, off);
        if (tid == 0) {
            float rate = sigm(v + r2b[0]);
            g_rate[b] = rate;
            out[RATEBASE + (long long)(t + 1) * BB + b] = rate;
        }
    }
}

// =================================================================================
extern "C" void kernel_launch(void* const* d_in, const int* in_sizes, int n_in,
                              void* d_out, int out_size) {
    const float* src      = (const float*)d_in[0];
    const int*   src_len  = (const int*)  d_in[1];
    const int*   trg_eid  = (const int*)  d_in[2];
    const float* trg_rate = (const float*)d_in[3];
    const float* emb      = (const float*)d_in[4];
    const float* enc_Wih  = (const float*)d_in[5];
    const float* enc_Whh  = (const float*)d_in[6];
    const float* enc_bih  = (const float*)d_in[7];
    const float* enc_bhh  = (const float*)d_in[8];
    const float* dec_Wih  = (const float*)d_in[9];
    const float* dec_Whh  = (const float*)d_in[10];
    const float* dec_bih  = (const float*)d_in[11];
    const float* dec_bhh  = (const float*)d_in[12];
    const float* pe_W     = (const float*)d_in[13];
    const float* pe_b     = (const float*)d_in[14];
    const float* r1_W     = (const float*)d_in[15];
    const float* r1_b     = (const float*)d_in[16];
    const float* r2_W     = (const float*)d_in[17];
    const float* r2_b     = (const float*)d_in[18];
    float* out = (float*)d_out;

    prep_kernel<<<(int)((EIDSLAB + 255) / 256), 256>>>(out, trg_eid, trg_rate);

    for (int t = 0; t < TSRC; t++)
        enc_gru_kernel<<<128, 256>>>(src, src_len, enc_Wih, enc_Whh, enc_bih, enc_bhh,
                                     t, t & 1);
    // h ends in g_hA (200 steps, even count)

    for (int d = 0; d < TTRG - 1; d++) {
        int dir  = d & 1;        // 0: A->B, 1: B->A
        int hsel = dir ^ 1;      // buffer holding the freshly written h
        dec_gru_kernel<<<128, 256>>>(emb, dec_Wih, dec_Whh, dec_bih, dec_bhh, dir);
        pe_gemm_kernel<<<157, 256>>>(pe_W, pe_b, out, d, hsel);
        softmax_argmax_kernel<<<64, 1024>>>(out, d);
        r1rate_kernel<<<64, 512>>>(emb, r1_W, r1_b, r2_W, r2_b, out, d, hsel);
    }
}

// round 11
// speedup vs baseline: 1.0084x; 1.0084x over previous
#include <cuda_runtime.h>
#include <cuda_bf16.h>
#include <math.h>

// Problem constants
#define BB   64
#define HH   512
#define EE   256
#define VV   20000
#define TSRC 200
#define TTRG 128
#define EIDSLAB  ((long long)BB * VV)             // floats per output timestep
#define RATEBASE ((long long)TTRG * BB * VV)      // offset of rate block in d_out

// ---------------- device scratch (static; no runtime allocation) ----------------
__device__ float g_hA[BB * HH];
__device__ float g_hB[BB * HH];
__device__ int   g_eid[BB];
__device__ float g_rate[BB];

// ---------------- packed fp32x2 helpers (sm_103a FMA2 path) ----------------
__device__ __forceinline__ unsigned long long pk2(float a, float b) {
    unsigned long long r;
    asm("mov.b64 %0, {%1,%2};" : "=l"(r) : "f"(a), "f"(b));
    return r;
}
__device__ __forceinline__ void fma2(unsigned long long& acc,
                                     unsigned long long a, unsigned long long w) {
    asm("fma.rn.f32x2 %0, %1, %2, %0;" : "+l"(acc) : "l"(a), "l"(w));
}
__device__ __forceinline__ float upk2(unsigned long long a) {
    float lo = __uint_as_float((unsigned)a);
    float hi = __uint_as_float((unsigned)(a >> 32));
    return lo + hi;
}
__device__ __forceinline__ float sigm(float x) { return 1.0f / (1.0f + expf(-x)); }

// =================================================================================
// prep: zero step-0 output slabs, init h0, eid0, rate0
// =================================================================================
__global__ void prep_kernel(float* __restrict__ out,
                            const int* __restrict__ trg_eid,
                            const float* __restrict__ trg_rate) {
    long long i = (long long)blockIdx.x * 256 + threadIdx.x;
    if (i < EIDSLAB) out[i] = 0.0f;
    if (i < BB) {
        out[RATEBASE + i] = 0.0f;
        g_eid[i]  = trg_eid[i];
        g_rate[i] = trg_rate[i];
    }
    if (i < BB * HH) g_hA[i] = 0.0f;
}

// =================================================================================
// Encoder GRU step. grid 128 x 256 threads. thread = (b, jj); block covers 4 h-cols.
// =================================================================================
__global__ __launch_bounds__(256) void enc_gru_kernel(
    const float* __restrict__ src,     // [200][64][3]
    const int*   __restrict__ src_len, // [64]
    const float* __restrict__ Wih,     // [1536][3]
    const float* __restrict__ Whh,     // [1536][512]
    const float* __restrict__ bih,
    const float* __restrict__ bhh,
    int t, int dir)
{
    const float* hin  = dir ? g_hB : g_hA;
    float*       hout = dir ? g_hA : g_hB;

    __shared__ __align__(16) float Hs[64 * 34];   // [b][k], stride 34 (8B-aligned pairs)
    __shared__ __align__(16) float Ws[12 * 34];   // 3 gates x 4 cols

    int tid = threadIdx.x;
    int b  = tid & 63;
    int jj = tid >> 6;
    int j0 = blockIdx.x * 4;
    int j  = j0 + jj;

    unsigned long long a0 = 0ull, a1 = 0ull, a2 = 0ull;

    for (int k0 = 0; k0 < HH; k0 += 32) {
        __syncthreads();
        #pragma unroll
        for (int p = 0; p < 8; p++) {
            int idx = tid + p * 256;
            int r = idx >> 5, k = idx & 31;
            Hs[r * 34 + k] = hin[r * HH + k0 + k];
        }
        for (int idx = tid; idx < 384; idx += 256) {
            int wr = idx >> 5, k = idx & 31;
            Ws[wr * 34 + k] = Whh[((wr >> 2) * HH + j0 + (wr & 3)) * HH + k0 + k];
        }
        __syncthreads();
        #pragma unroll
        for (int kp = 0; kp < 16; kp++) {
            unsigned long long a = *(const unsigned long long*)&Hs[b * 34 + 2 * kp];
            fma2(a0, a, *(const unsigned long long*)&Ws[jj * 34 + 2 * kp]);
            fma2(a1, a, *(const unsigned long long*)&Ws[(4 + jj) * 34 + 2 * kp]);
            fma2(a2, a, *(const unsigned long long*)&Ws[(8 + jj) * 34 + 2 * kp]);
        }
    }

    const float* xt = src + ((long long)t * BB + b) * 3;
    float x0 = xt[0], x1 = xt[1], x2 = xt[2];
    int rr = j, rz = HH + j, rn = 2 * HH + j;
    float gir = bih[rr] + x0 * Wih[rr * 3] + x1 * Wih[rr * 3 + 1] + x2 * Wih[rr * 3 + 2];
    float giz = bih[rz] + x0 * Wih[rz * 3] + x1 * Wih[rz * 3 + 1] + x2 * Wih[rz * 3 + 2];
    float gin = bih[rn] + x0 * Wih[rn * 3] + x1 * Wih[rn * 3 + 1] + x2 * Wih[rn * 3 + 2];

    float ghr = upk2(a0) + bhh[rr];
    float ghz = upk2(a1) + bhh[rz];
    float ghn = upk2(a2) + bhh[rn];

    float r = sigm(gir + ghr);
    float z = sigm(giz + ghz);
    float n = tanhf(gin + r * ghn);
    float hprev = hin[b * HH + j];
    float hnew  = (1.0f - z) * n + z * hprev;
    hout[b * HH + j] = (t < src_len[b]) ? hnew : hprev;
}

// =================================================================================
// Decoder GRU step. K = 512 (Whh over h) + 257 (Wih over [emb[eid], rate]).
// =================================================================================
__global__ __launch_bounds__(256) void dec_gru_kernel(
    const float* __restrict__ emb,     // [20000][256]
    const float* __restrict__ Wih,     // [1536][257]
    const float* __restrict__ Whh,     // [1536][512]
    const float* __restrict__ bih,
    const float* __restrict__ bhh,
    int dir)
{
    const float* hin  = dir ? g_hB : g_hA;
    float*       hout = dir ? g_hA : g_hB;

    __shared__ __align__(16) float Hs[64 * 34];
    __shared__ __align__(16) float Ws[12 * 34];

    int tid = threadIdx.x;
    int b  = tid & 63;
    int jj = tid >> 6;
    int j0 = blockIdx.x * 4;
    int j  = j0 + jj;

    unsigned long long aH0 = 0, aH1 = 0, aH2 = 0;
    unsigned long long aI0 = 0, aI1 = 0, aI2 = 0;

    // ---- h @ Whh^T part (K = 512) ----
    for (int k0 = 0; k0 < HH; k0 += 32) {
        __syncthreads();
        #pragma unroll
        for (int p = 0; p < 8; p++) {
            int idx = tid + p * 256;
            int r = idx >> 5, k = idx & 31;
            Hs[r * 34 + k] = hin[r * HH + k0 + k];
        }
        for (int idx = tid; idx < 384; idx += 256) {
            int wr = idx >> 5, k = idx & 31;
            Ws[wr * 34 + k] = Whh[((wr >> 2) * HH + j0 + (wr & 3)) * HH + k0 + k];
        }
        __syncthreads();
        #pragma unroll
        for (int kp = 0; kp < 16; kp++) {
            unsigned long long a = *(const unsigned long long*)&Hs[b * 34 + 2 * kp];
            fma2(aH0, a, *(const unsigned long long*)&Ws[jj * 34 + 2 * kp]);
            fma2(aH1, a, *(const unsigned long long*)&Ws[(4 + jj) * 34 + 2 * kp]);
            fma2(aH2, a, *(const unsigned long long*)&Ws[(8 + jj) * 34 + 2 * kp]);
        }
    }

    // ---- emb[eid] @ Wih^T part (K = 256; Wih row stride 257) ----
    for (int k0 = 0; k0 < EE; k0 += 32) {
        __syncthreads();
        #pragma unroll
        for (int p = 0; p < 8; p++) {
            int idx = tid + p * 256;
            int r = idx >> 5, k = idx & 31;
            Hs[r * 34 + k] = emb[(long long)g_eid[r] * EE + k0 + k];
        }
        for (int idx = tid; idx < 384; idx += 256) {
            int wr = idx >> 5, k = idx & 31;
            Ws[wr * 34 + k] = Wih[((wr >> 2) * HH + j0 + (wr & 3)) * 257 + k0 + k];
        }
        __syncthreads();
        #pragma unroll
        for (int kp = 0; kp < 16; kp++) {
            unsigned long long a = *(const unsigned long long*)&Hs[b * 34 + 2 * kp];
            fma2(aI0, a, *(const unsigned long long*)&Ws[jj * 34 + 2 * kp]);
            fma2(aI1, a, *(const unsigned long long*)&Ws[(4 + jj) * 34 + 2 * kp]);
            fma2(aI2, a, *(const unsigned long long*)&Ws[(8 + jj) * 34 + 2 * kp]);
        }
    }

    int rr = j, rz = HH + j, rn = 2 * HH + j;
    float rate = g_rate[b];
    float gir = upk2(aI0) + bih[rr] + rate * Wih[rr * 257 + 256];
    float giz = upk2(aI1) + bih[rz] + rate * Wih[rz * 257 + 256];
    float gin = upk2(aI2) + bih[rn] + rate * Wih[rn * 257 + 256];
    float ghr = upk2(aH0) + bhh[rr];
    float ghz = upk2(aH1) + bhh[rz];
    float ghn = upk2(aH2) + bhh[rn];

    float r = sigm(gir + ghr);
    float z = sigm(giz + ghz);
    float n = tanhf(gin + r * ghn);
    float hprev = hin[b * HH + j];
    hout[b * HH + j] = (1.0f - z) * n + z * hprev;
}

// =================================================================================
// pe GEMM: logits[b][v] = dot(h[b], pe_W[v]) + pe_b[v] -> written into out slab t+1.
// grid 157 x 256 threads; tile 64b x 128v; thread = 8b x 4v packed accumulators.
// =================================================================================
__global__ __launch_bounds__(256) void pe_gemm_kernel(
    const float* __restrict__ peW,   // [20000][512]
    const float* __restrict__ peB,   // [20000]
    float* __restrict__ out, int t, int hsel)
{
    const float* h = hsel ? g_hB : g_hA;

    __shared__ __align__(16) float Hs[64 * 34];
    __shared__ __align__(16) float Ws[128 * 34];

    int tid = threadIdx.x;
    int ty = tid >> 5;           // 0..7 -> b group
    int tx = tid & 31;           // v lane
    int b0 = ty * 8;
    int v0 = blockIdx.x * 128;

    unsigned long long acc[8][4];
    #pragma unroll
    for (int i = 0; i < 8; i++)
        #pragma unroll
        for (int jv = 0; jv < 4; jv++) acc[i][jv] = 0ull;

    for (int k0 = 0; k0 < HH; k0 += 32) {
        __syncthreads();
        #pragma unroll
        for (int p = 0; p < 8; p++) {
            int idx = tid + p * 256;
            int r = idx >> 5, k = idx & 31;
            Hs[r * 34 + k] = h[r * HH + k0 + k];
        }
        #pragma unroll
        for (int p = 0; p < 16; p++) {
            int idx = tid + p * 256;
            int r = idx >> 5, k = idx & 31;
            int v = v0 + r;
            Ws[r * 34 + k] = (v < VV) ? peW[v * HH + k0 + k] : 0.0f;
        }
        __syncthreads();
        #pragma unroll
        for (int kp = 0; kp < 16; kp++) {
            unsigned long long a[8], w[4];
            #pragma unroll
            for (int i = 0; i < 8; i++)
                a[i] = *(const unsigned long long*)&Hs[(b0 + i) * 34 + 2 * kp];
            #pragma unroll
            for (int jv = 0; jv < 4; jv++)
                w[jv] = *(const unsigned long long*)&Ws[(tx + 32 * jv) * 34 + 2 * kp];
            #pragma unroll
            for (int i = 0; i < 8; i++)
                #pragma unroll
                for (int jv = 0; jv < 4; jv++)
                    fma2(acc[i][jv], a[i], w[jv]);
        }
    }

    long long slab = (long long)(t + 1) * EIDSLAB;
    #pragma unroll
    for (int jv = 0; jv < 4; jv++) {
        int v = v0 + tx + 32 * jv;
        if (v < VV) {
            float bias = peB[v];
            #pragma unroll
            for (int i = 0; i < 8; i++)
                out[slab + (long long)(b0 + i) * VV + v] = upk2(acc[i][jv]) + bias;
        }
    }
}

// =================================================================================
// Fused log_softmax + argmax per row. grid 64 x 1024 threads, 20 logits/thread
// held in registers; single global read + single write. Writes g_eid.
// =================================================================================
__global__ __launch_bounds__(1024) void softmax_argmax_kernel(float* __restrict__ out, int t)
{
    int b   = blockIdx.x;
    int tid = threadIdx.x;
    float* row = out + (long long)(t + 1) * EIDSLAB + (long long)b * VV;

    float vals[20];
    float m = -INFINITY;
    int   mi = 0;
    #pragma unroll
    for (int i = 0; i < 20; i++) {
        int idx = tid + (i << 10);
        float v = (idx < VV) ? row[idx] : -INFINITY;
        vals[i] = v;
        if (v > m) { m = v; mi = idx; }
    }

    __shared__ float sm[32];
    __shared__ int   si[32];
    __shared__ float g0, g1;
    __shared__ int   gidx;

    int wid = tid >> 5, lane = tid & 31;
    #pragma unroll
    for (int off = 16; off; off >>= 1) {
        float om = __shfl_down_sync(0xffffffffu, m, off);
        int   oi = __shfl_down_sync(0xffffffffu, mi, off);
        if (om > m || (om == m && oi < mi)) { m = om; mi = oi; }
    }
    if (lane == 0) { sm[wid] = m; si[wid] = mi; }
    __syncthreads();
    if (wid == 0) {
        m  = sm[lane];
        mi = si[lane];
        #pragma unroll
        for (int off = 16; off; off >>= 1) {
            float om = __shfl_down_sync(0xffffffffu, m, off);
            int   oi = __shfl_down_sync(0xffffffffu, mi, off);
            if (om > m || (om == m && oi < mi)) { m = om; mi = oi; }
        }
        if (lane == 0) { g0 = m; gidx = mi; }
    }
    __syncthreads();
    float gmax = g0;

    float s = 0.0f;
    #pragma unroll
    for (int i = 0; i < 20; i++) {
        int idx = tid + (i << 10);
        if (idx < VV) s += expf(vals[i] - gmax);
    }
    #pragma unroll
    for (int off = 16; off; off >>= 1)
        s += __shfl_down_sync(0xffffffffu, s, off);
    if (lane == 0) sm[wid] = s;
    __syncthreads();
    if (wid == 0) {
        s = sm[lane];
        #pragma unroll
        for (int off = 16; off; off >>= 1)
            s += __shfl_down_sync(0xffffffffu, s, off);
        if (lane == 0) g1 = gmax + logf(s);
    }
    __syncthreads();
    float logZ = g1;

    #pragma unroll
    for (int i = 0; i < 20; i++) {
        int idx = tid + (i << 10);
        if (idx < VV) row[idx] = vals[i] - logZ;
    }
    if (tid == 0) g_eid[b] = gidx;
}

// =================================================================================
// r1 = relu([emb[idx], h] @ r1_W^T + r1_b); rate = sigmoid(r1 . r2_W + r2_b).
// grid 64 (one block per b) x 512 threads (one per r1 column).
// =================================================================================
__global__ __launch_bounds__(512) void r1rate_kernel(
    const float* __restrict__ emb,
    const float* __restrict__ r1W,   // [512][768]
    const float* __restrict__ r1b,
    const float* __restrict__ r2W,   // [1][512]
    const float* __restrict__ r2b,
    float* __restrict__ out, int t, int hsel)
{
    const float* h = hsel ? g_hB : g_hA;
    int b   = blockIdx.x;
    int tid = threadIdx.x;

    __shared__ __align__(16) float Xs[768];
    __shared__ float sred[16];

    if (tid < 256) Xs[tid] = emb[(long long)g_eid[b] * EE + tid];
    Xs[256 + tid] = h[b * HH + tid];
    __syncthreads();

    const float4* wp = (const float4*)(r1W + tid * 768);
    unsigned long long a0 = 0ull, a1 = 0ull;
    #pragma unroll 4
    for (int q = 0; q < 192; q++) {
        float4 w4 = wp[q];
        float4 x4 = *(const float4*)&Xs[4 * q];
        fma2(a0, pk2(x4.x, x4.y), pk2(w4.x, w4.y));
        fma2(a1, pk2(x4.z, x4.w), pk2(w4.z, w4.w));
    }
    float r1v = upk2(a0) + upk2(a1) + r1b[tid];
    float s = fmaxf(r1v, 0.0f) * r2W[tid];

    int lane = tid & 31, wid = tid >> 5;
    #pragma unroll
    for (int off = 16; off; off >>= 1)
        s += __shfl_down_sync(0xffffffffu, s, off);
    if (lane == 0) sred[wid] = s;
    __syncthreads();
    if (tid < 32) {
        float v = (tid < 16) ? sred[tid] : 0.0f;
        #pragma unroll
        for (int off = 8; off; off >>= 1)
            v += __shfl_down_sync(0xffffffffu, v, off);
        if (tid == 0) {
            float rate = sigm(v + r2b[0]);
            g_rate[b] = rate;
            out[RATEBASE + (long long)(t + 1) * BB + b] = rate;
        }
    }
}

// =================================================================================
extern "C" void kernel_launch(void* const* d_in, const int* in_sizes, int n_in,
                              void* d_out, int out_size) {
    const float* src      = (const float*)d_in[0];
    const int*   src_len  = (const int*)  d_in[1];
    const int*   trg_eid  = (const int*)  d_in[2];
    const float* trg_rate = (const float*)d_in[3];
    const float* emb      = (const float*)d_in[4];
    const float* enc_Wih  = (const float*)d_in[5];
    const float* enc_Whh  = (const float*)d_in[6];
    const float* enc_bih  = (const float*)d_in[7];
    const float* enc_bhh  = (const float*)d_in[8];
    const float* dec_Wih  = (const float*)d_in[9];
    const float* dec_Whh  = (const float*)d_in[10];
    const float* dec_bih  = (const float*)d_in[11];
    const float* dec_bhh  = (const float*)d_in[12];
    const float* pe_W     = (const float*)d_in[13];
    const float* pe_b     = (const float*)d_in[14];
    const float* r1_W     = (const float*)d_in[15];
    const float* r1_b     = (const float*)d_in[16];
    const float* r2_W     = (const float*)d_in[17];
    const float* r2_b     = (const float*)d_in[18];
    float* out = (float*)d_out;

    prep_kernel<<<(int)((EIDSLAB + 255) / 256), 256>>>(out, trg_eid, trg_rate);

    for (int t = 0; t < TSRC; t++)
        enc_gru_kernel<<<128, 256>>>(src, src_len, enc_Wih, enc_Whh, enc_bih, enc_bhh,
                                     t, t & 1);
    // h ends in g_hA (200 steps, even count)

    for (int d = 0; d < TTRG - 1; d++) {
        int dir  = d & 1;        // 0: A->B, 1: B->A
        int hsel = dir ^ 1;      // buffer holding the freshly written h
        dec_gru_kernel<<<128, 256>>>(emb, dec_Wih, dec_Whh, dec_bih, dec_bhh, dir);
        pe_gemm_kernel<<<157, 256>>>(pe_W, pe_b, out, d, hsel);
        softmax_argmax_kernel<<<64, 1024>>>(out, d);
        r1rate_kernel<<<64, 512>>>(emb, r1_W, r1_b, r2_W, r2_b, out, d, hsel);
    }
}